// round 3
// baseline (speedup 1.0000x reference)
#include <cuda_runtime.h>
#include <cstdint>
#include <cstddef>

#define SEQ   512
#define DIM   256
#define HID   1024
#define BATCH 128
#define KTOT  1280
#define TSTEP 512
#define COUT  10

#define NCTA  64
#define NTHR  256
#define CH_K  32      // K-chunk per stage
#define NCH   40      // 1280 / 32
#define AS_LD 36      // padded row stride (floats) -> conflict-free frag reads

// ---------------- device scratch (no allocations allowed) ----------------
__device__ float2   g_Wf[512u * 160u * 32u];   // packed B fragments: [gt][kt][lane]{r0,r1}  (21 MB)
__device__ float    g_bcat[4 * HID];           // fused bias [gate*1024 + j]
__device__ float    g_h[2][BATCH * HID];       // double-buffered hidden state
__device__ unsigned g_bar;                     // monotonic grid barrier counter

// ---------------- helpers ----------------
__device__ __forceinline__ float tf32_rn(float x) {
    uint32_t u;
    asm("cvt.rna.tf32.f32 %0, %1;" : "=r"(u) : "f"(x));
    return __uint_as_float(u);
}

__device__ __forceinline__ float sig_f(float x) {
    float ax = fabsf(x);
    float e  = __expf(-ax);
    float s  = __fdividef(1.0f, 1.0f + e);
    return (x >= 0.0f) ? s : (1.0f - s);
}

__device__ __forceinline__ float tanh_f(float x) {
    float ax = fabsf(x);
    float e  = __expf(-2.0f * ax);
    float t  = __fdividef(1.0f - e, 1.0f + e);
    return copysignf(t, x);
}

__device__ __forceinline__ void grid_bar(unsigned target) {
    __syncthreads();
    if (threadIdx.x == 0) {
        __threadfence();                       // release this CTA's writes
        atomicAdd(&g_bar, 1u);
        unsigned v;
        do {
            asm volatile("ld.global.acquire.gpu.u32 %0, [%1];"
                         : "=r"(v) : "l"(&g_bar));
        } while (v < target);
    }
    __syncthreads();
}

__device__ __forceinline__ void mma_tf32(float* c, const uint32_t* a, float2 b) {
    uint32_t b0 = __float_as_uint(b.x);
    uint32_t b1 = __float_as_uint(b.y);
    asm volatile(
        "mma.sync.aligned.m16n8k8.row.col.f32.tf32.tf32.f32 "
        "{%0,%1,%2,%3}, {%4,%5,%6,%7}, {%8,%9}, {%0,%1,%2,%3};\n"
        : "+f"(c[0]), "+f"(c[1]), "+f"(c[2]), "+f"(c[3])
        : "r"(a[0]), "r"(a[1]), "r"(a[2]), "r"(a[3]), "r"(b0), "r"(b1));
}

// ---------------- setup: pack W into mma-B fragment layout (tf32, RN) ----------------
__global__ void pack_kernel(
    const float* __restrict__ Wgx, const float* __restrict__ Wix,
    const float* __restrict__ Wfx, const float* __restrict__ Wox,
    const float* __restrict__ Wgh, const float* __restrict__ Wih,
    const float* __restrict__ Wfh, const float* __restrict__ Woh,
    const float* __restrict__ bg,  const float* __restrict__ bi,
    const float* __restrict__ bf_, const float* __restrict__ bo)
{
    unsigned idx = blockIdx.x * blockDim.x + threadIdx.x;
    if (idx == 0) g_bar = 0u;                  // reset barrier for this replay
    if (idx < 4u * HID) {
        int gate = idx >> 10, j = idx & (HID - 1);
        const float* bp = (gate == 0) ? bg : (gate == 1) ? bi : (gate == 2) ? bf_ : bo;
        g_bcat[idx] = bp[j];
    }
    if (idx >= 512u * 160u * 32u) return;

    int lane = idx & 31;
    unsigned rest = idx >> 5;
    int kt  = rest % 160;
    int gt  = rest / 160;
    int nt  = gt & 7, cta = gt >> 3;
    int gate = nt & 3, jj = nt >> 2;
    int j = cta * 16 + jj * 8 + (lane >> 2);   // n within B-frag = lane/4
    int k = kt * 8 + (lane & 3);               // r0: k, r1: k+4

    const float* Wx = (gate == 0) ? Wgx : (gate == 1) ? Wix : (gate == 2) ? Wfx : Wox;
    const float* Wh = (gate == 0) ? Wgh : (gate == 1) ? Wih : (gate == 2) ? Wfh : Woh;

    float v0, v1;
    if (k < DIM) { v0 = Wx[k * HID + j];          v1 = Wx[(k + 4) * HID + j]; }
    else         { v0 = Wh[(k - DIM) * HID + j];  v1 = Wh[(k + 4 - DIM) * HID + j]; }

    g_Wf[idx] = make_float2(tf32_rn(v0), tf32_rn(v1));
}

// ---------------- persistent LSTM kernel ----------------
__global__ void __launch_bounds__(NTHR, 1)
lstm_kernel(const float* __restrict__ x,
            const float* __restrict__ Wph,
            const float* __restrict__ bp,
            float* __restrict__ out)
{
    __shared__ __align__(16) float As[2][BATCH][AS_LD];

    const int tid   = threadIdx.x;
    const int cta   = blockIdx.x;
    const int wid   = tid >> 5;
    const int lane  = tid & 31;
    const int warpM = wid & 3;                 // 4 row-groups of 32
    const int warpN = wid >> 2;                // 2 j-groups of 8
    const int lk    = lane & 3;
    const int lg    = lane >> 2;

    // staging assignment: each thread stages 16 consecutive k of one row
    const int srow = tid >> 1;                 // 0..127
    const int sk4  = (tid & 1) * 16;           // 0 or 16

    // zero h0
    for (int i = cta * NTHR + tid; i < BATCH * HID; i += NCTA * NTHR)
        g_h[0][i] = 0.0f;
    grid_bar(1u * NCTA);

    // per-thread persistent cell state + bias
    float creg[2][4];
    #pragma unroll
    for (int m = 0; m < 2; m++)
        #pragma unroll
        for (int q = 0; q < 4; q++) creg[m][q] = 0.0f;

    const int j0 = cta * 16 + warpN * 8 + 2 * lk;
    float bias[4][2];
    #pragma unroll
    for (int g = 0; g < 4; g++) {
        bias[g][0] = g_bcat[g * HID + j0];
        bias[g][1] = g_bcat[g * HID + j0 + 1];
    }

    for (int t = 0; t < TSTEP; t++) {
        float acc[2][4][4];
        #pragma unroll
        for (int m = 0; m < 2; m++)
            #pragma unroll
            for (int g = 0; g < 4; g++)
                #pragma unroll
                for (int q = 0; q < 4; q++) acc[m][g][q] = 0.0f;

        const float* hin = g_h[t & 1];

        // preload chunk 0 (x part)
        {
            const float* s = x + ((size_t)srow * SEQ + (size_t)t) * DIM + sk4;
            float* p = &As[0][srow][sk4];
            #pragma unroll
            for (int i = 0; i < 4; i++) {
                float4 v = *(const float4*)(s + 4 * i);
                v.x = tf32_rn(v.x); v.y = tf32_rn(v.y);
                v.z = tf32_rn(v.z); v.w = tf32_rn(v.w);
                *(float4*)(p + 4 * i) = v;
            }
        }

        int buf = 0;
        const int rb = warpM * 32 + lg;

        for (int ch = 0; ch < NCH; ch++) {
            __syncthreads();

            // prefetch next chunk into registers (overlaps with mma below)
            float4 nx[4];
            const bool more = (ch + 1 < NCH);
            if (more) {
                const int kg = (ch + 1) * CH_K + sk4;
                const float* s = (ch + 1 < 8)
                    ? x + ((size_t)srow * SEQ + (size_t)t) * DIM + kg
                    : hin + srow * HID + (kg - DIM);
                #pragma unroll
                for (int i = 0; i < 4; i++) nx[i] = *(const float4*)(s + 4 * i);
            }

            // compute over As[buf]
            #pragma unroll
            for (int kt4 = 0; kt4 < 4; kt4++) {
                const int kb = kt4 * 8 + lk;
                uint32_t a0[4], a1[4];
                a0[0] = __float_as_uint(As[buf][rb     ][kb    ]);
                a0[1] = __float_as_uint(As[buf][rb +  8][kb    ]);
                a0[2] = __float_as_uint(As[buf][rb     ][kb + 4]);
                a0[3] = __float_as_uint(As[buf][rb +  8][kb + 4]);
                a1[0] = __float_as_uint(As[buf][rb + 16][kb    ]);
                a1[1] = __float_as_uint(As[buf][rb + 24][kb    ]);
                a1[2] = __float_as_uint(As[buf][rb + 16][kb + 4]);
                a1[3] = __float_as_uint(As[buf][rb + 24][kb + 4]);

                const int ktg = ch * 4 + kt4;
                #pragma unroll
                for (int g = 0; g < 4; g++) {
                    float2 bv = g_Wf[((unsigned)(cta * 8 + warpN * 4 + g) * 160u + ktg) * 32u + lane];
                    mma_tf32(acc[0][g], a0, bv);
                    mma_tf32(acc[1][g], a1, bv);
                }
            }

            if (more) {
                float* p = &As[buf ^ 1][srow][sk4];
                #pragma unroll
                for (int i = 0; i < 4; i++) {
                    float4 v = nx[i];
                    v.x = tf32_rn(v.x); v.y = tf32_rn(v.y);
                    v.z = tf32_rn(v.z); v.w = tf32_rn(v.w);
                    *(float4*)(p + 4 * i) = v;
                }
                buf ^= 1;
            }
        }

        // gates + cell update + h write (fully in-register gate fusion)
        float* hout = g_h[(t + 1) & 1];
        #pragma unroll
        for (int m = 0; m < 2; m++) {
            #pragma unroll
            for (int q = 0; q < 4; q++) {
                const int row = warpM * 32 + m * 16 + lg + ((q & 2) ? 8 : 0);
                const int j   = j0 + (q & 1);
                float zg = acc[m][0][q] + bias[0][q & 1];
                float zi = acc[m][1][q] + bias[1][q & 1];
                float zf = acc[m][2][q] + bias[2][q & 1];
                float zo = acc[m][3][q] + bias[3][q & 1];
                float gg = tanh_f(zg);
                float ii = sig_f(zi);
                float ff = sig_f(zf);
                float oo = sig_f(zo);
                float c  = gg * ii + creg[m][q] * ff;
                creg[m][q] = c;
                hout[row * HID + j] = tanh_f(c) * oo;
            }
        }

        grid_bar((unsigned)(t + 2) * NCTA);
    }

    // final projection: out = h_T @ W_ph + b_p  (h_T lives in g_h[0])
    const float* hfin = g_h[0];
    const int gw = cta * 8 + wid;              // 0..511 global warp id
    for (int e = gw; e < BATCH * COUT; e += NCTA * 8) {
        const int b  = e / COUT;
        const int cc = e - b * COUT;
        float s = 0.0f;
        for (int j = lane; j < HID; j += 32)
            s += hfin[b * HID + j] * Wph[j * COUT + cc];
        #pragma unroll
        for (int off = 16; off; off >>= 1)
            s += __shfl_down_sync(0xFFFFFFFFu, s, off);
        if (lane == 0) out[e] = s + bp[cc];
    }
}

// ---------------- launch ----------------
extern "C" void kernel_launch(void* const* d_in, const int* in_sizes, int n_in,
                              void* d_out, int out_size)
{
    const float* x = (const float*)d_in[0];
    const float *Wgx, *Wix, *Wfx, *Wox, *Wgh, *Wih, *Wfh, *Woh;
    const float *bg, *bi, *bf_, *bo, *Wph, *bp;

    // Detect input ordering from sizes.
    // setup_inputs() dict order (expected): x, W_gx, W_gh, b_g, W_ix, W_ih, b_i,
    //   W_fx, W_fh, b_f, W_ox, W_oh, b_o, W_ph, b_p
    //   -> in_sizes[2] == HID*HID (W_gh)
    // reference() signature order (fallback): x, W_gx, W_ix, W_fx, W_ox, W_gh, ...
    //   -> in_sizes[2] == DIM*HID (W_ix)
    if (in_sizes[2] == HID * HID) {
        Wgx = (const float*)d_in[1];  Wgh = (const float*)d_in[2];  bg  = (const float*)d_in[3];
        Wix = (const float*)d_in[4];  Wih = (const float*)d_in[5];  bi  = (const float*)d_in[6];
        Wfx = (const float*)d_in[7];  Wfh = (const float*)d_in[8];  bf_ = (const float*)d_in[9];
        Wox = (const float*)d_in[10]; Woh = (const float*)d_in[11]; bo  = (const float*)d_in[12];
        Wph = (const float*)d_in[13]; bp  = (const float*)d_in[14];
    } else {
        Wgx = (const float*)d_in[1];  Wix = (const float*)d_in[2];
        Wfx = (const float*)d_in[3];  Wox = (const float*)d_in[4];
        Wgh = (const float*)d_in[5];  Wih = (const float*)d_in[6];
        Wfh = (const float*)d_in[7];  Woh = (const float*)d_in[8];
        bg  = (const float*)d_in[9];  bi  = (const float*)d_in[10];
        bf_ = (const float*)d_in[11]; bo  = (const float*)d_in[12];
        Wph = (const float*)d_in[13]; bp  = (const float*)d_in[14];
    }

    // pack weights into fragment layout + reset barrier (runs every replay)
    const unsigned total = 512u * 160u * 32u;
    pack_kernel<<<(total + 255) / 256, 256>>>(Wgx, Wix, Wfx, Wox,
                                              Wgh, Wih, Wfh, Woh,
                                              bg, bi, bf_, bo);

    lstm_kernel<<<NCTA, NTHR>>>(x, Wph, bp, (float*)d_out);
}

// round 4
// speedup vs baseline: 1.4875x; 1.4875x over previous
#include <cuda_runtime.h>
#include <cstdint>
#include <cstddef>

#define SEQ   512
#define DIM   256
#define HID   1024
#define BATCH 128
#define KTOT  1280
#define TSTEP 512
#define COUT  10

#define NCTA  128
#define NTHR  256
#define CH_K  32      // K-chunk per stage
#define NCH   40      // 1280 / 32
#define NBUF  3       // cp.async pipeline depth-2

// ---------------- device scratch (no allocations allowed) ----------------
// packed B fragments: [cta*4+gate][ktg][lane]{r0,r1}  (512*160*32 float2 = 21 MB)
__device__ float2   g_Wf[512u * 160u * 32u];
__device__ float    g_bcat[4 * HID];           // fused bias [gate*1024 + j]
__device__ float    g_h[2][BATCH * HID];       // double-buffered hidden state
__device__ unsigned g_bar;                     // monotonic grid barrier counter

// ---------------- helpers ----------------
__device__ __forceinline__ uint32_t tf32u(float x) {
    uint32_t u;
    asm("cvt.rna.tf32.f32 %0, %1;" : "=r"(u) : "f"(x));
    return u;
}
__device__ __forceinline__ float tf32_rn(float x) { return __uint_as_float(tf32u(x)); }

__device__ __forceinline__ float sig_f(float x) {
    float ax = fabsf(x);
    float e  = __expf(-ax);
    float s  = __fdividef(1.0f, 1.0f + e);
    return (x >= 0.0f) ? s : (1.0f - s);
}

__device__ __forceinline__ float tanh_f(float x) {
    float ax = fabsf(x);
    float e  = __expf(-2.0f * ax);
    float t  = __fdividef(1.0f - e, 1.0f + e);
    return copysignf(t, x);
}

__device__ __forceinline__ void grid_bar(unsigned target) {
    __syncthreads();
    if (threadIdx.x == 0) {
        __threadfence();                       // release this CTA's writes
        atomicAdd(&g_bar, 1u);
        unsigned v;
        do {
            asm volatile("ld.global.acquire.gpu.u32 %0, [%1];"
                         : "=r"(v) : "l"(&g_bar));
        } while (v < target);
    }
    __syncthreads();
}

__device__ __forceinline__ void mma_tf32(float* c, const uint32_t* a, float2 b) {
    uint32_t b0 = __float_as_uint(b.x);
    uint32_t b1 = __float_as_uint(b.y);
    asm volatile(
        "mma.sync.aligned.m16n8k8.row.col.f32.tf32.tf32.f32 "
        "{%0,%1,%2,%3}, {%4,%5,%6,%7}, {%8,%9}, {%0,%1,%2,%3};\n"
        : "+f"(c[0]), "+f"(c[1]), "+f"(c[2]), "+f"(c[3])
        : "r"(a[0]), "r"(a[1]), "r"(a[2]), "r"(a[3]), "r"(b0), "r"(b1));
}

// swizzled smem word index: 128B rows, 16B-block XOR swizzle -> conflict-free frags
__device__ __forceinline__ int sw_idx(int buf, int row, int kb) {
    return (buf * BATCH + row) * 32 + ((((kb >> 2) ^ (row & 7)) << 2) | (kb & 3));
}

// ---------------- setup: pack W into mma-B fragment layout (tf32, RN) ----------------
__global__ void pack_kernel(
    const float* __restrict__ Wgx, const float* __restrict__ Wix,
    const float* __restrict__ Wfx, const float* __restrict__ Wox,
    const float* __restrict__ Wgh, const float* __restrict__ Wih,
    const float* __restrict__ Wfh, const float* __restrict__ Woh,
    const float* __restrict__ bg,  const float* __restrict__ bi,
    const float* __restrict__ bf_, const float* __restrict__ bo)
{
    unsigned idx = blockIdx.x * blockDim.x + threadIdx.x;
    if (idx == 0) g_bar = 0u;                  // reset barrier for this replay
    if (idx < 4u * HID) {
        int gate = idx >> 10, j = idx & (HID - 1);
        const float* bp = (gate == 0) ? bg : (gate == 1) ? bi : (gate == 2) ? bf_ : bo;
        g_bcat[idx] = bp[j];
    }
    if (idx >= 512u * 160u * 32u) return;

    int lane = idx & 31;
    unsigned rest = idx >> 5;
    int kt  = rest % 160;                      // ktg: 8-k group 0..159
    int gt  = rest / 160;                      // 0..511 = cta*4 + gate
    int cta  = gt >> 2;
    int gate = gt & 3;
    int j = cta * 8 + (lane >> 2);             // n within B-frag = lane/4
    int k = kt * 8 + (lane & 3);               // r0: k, r1: k+4

    const float* Wx = (gate == 0) ? Wgx : (gate == 1) ? Wix : (gate == 2) ? Wfx : Wox;
    const float* Wh = (gate == 0) ? Wgh : (gate == 1) ? Wih : (gate == 2) ? Wfh : Woh;

    float v0, v1;
    if (k < DIM) { v0 = Wx[k * HID + j];          v1 = Wx[(k + 4) * HID + j]; }
    else         { v0 = Wh[(k - DIM) * HID + j];  v1 = Wh[(k + 4 - DIM) * HID + j]; }

    g_Wf[idx] = make_float2(tf32_rn(v0), tf32_rn(v1));
}

// ---------------- persistent LSTM kernel ----------------
__global__ void __launch_bounds__(NTHR, 1)
lstm_kernel(const float* __restrict__ x,
            const float* __restrict__ Wph,
            const float* __restrict__ bp,
            float* __restrict__ out)
{
    __shared__ __align__(16) float As[NBUF * BATCH * 32];   // 48 KB, swizzled

    const int tid   = threadIdx.x;
    const int cta   = blockIdx.x;
    const int wid   = tid >> 5;
    const int lane  = tid & 31;
    const int lk    = lane & 3;
    const int lg    = lane >> 2;

    // staging assignment: each thread stages 16 consecutive k of one row
    const int srow = tid >> 1;                 // 0..127
    const int sk4  = (tid & 1) * 16;           // 0 or 16
    const uint32_t sdst_base =
        (uint32_t)__cvta_generic_to_shared(As) + (uint32_t)(srow * 32) * 4u;

    // zero h0
    for (int i = cta * NTHR + tid; i < BATCH * HID; i += NCTA * NTHR)
        g_h[0][i] = 0.0f;
    grid_bar(1u * NCTA);

    // per-thread persistent cell state + bias
    float creg[4];
    #pragma unroll
    for (int q = 0; q < 4; q++) creg[q] = 0.0f;

    const int j0 = cta * 8 + 2 * lk;
    float bias[4][2];
    #pragma unroll
    for (int g = 0; g < 4; g++) {
        bias[g][0] = g_bcat[g * HID + j0];
        bias[g][1] = g_bcat[g * HID + j0 + 1];
    }

    const int rb = wid * 16 + lg;              // warp covers rows wid*16..+15
    const float2* __restrict__ wbase = g_Wf + ((size_t)(cta * 4) * 160u) * 32u + lane;

    for (int t = 0; t < TSTEP; t++) {
        float acc[4][4];
        #pragma unroll
        for (int g = 0; g < 4; g++)
            #pragma unroll
            for (int q = 0; q < 4; q++) acc[g][q] = 0.0f;

        const float* hin = g_h[t & 1];

        // stage one chunk into buffer bf via cp.async.cg (L1-bypass)
        auto stage = [&](int ch, int bf) {
            const int kg = ch * CH_K + sk4;
            const float* s = (ch < 8)
                ? x + ((size_t)srow * SEQ + (size_t)t) * DIM + kg
                : hin + srow * HID + (kg - DIM);
            const uint32_t dbase = sdst_base + (uint32_t)(bf * BATCH * 32) * 4u;
            #pragma unroll
            for (int i = 0; i < 4; i++) {
                int b  = (sk4 >> 2) + i;               // 16B block 0..7
                int sb = b ^ (srow & 7);
                uint32_t dst = dbase + (uint32_t)sb * 16u;
                asm volatile("cp.async.cg.shared.global [%0], [%1], 16;\n"
                             :: "r"(dst), "l"(s + 4 * i) : "memory");
            }
            asm volatile("cp.async.commit_group;\n" ::: "memory");
        };

        // prologue: chunks 0 and 1 in flight
        stage(0, 0);
        stage(1, 1);

        int buf = 0;
        for (int ch = 0; ch < NCH; ch++) {
            if (ch == NCH - 1) asm volatile("cp.async.wait_group 0;\n" ::: "memory");
            else               asm volatile("cp.async.wait_group 1;\n" ::: "memory");
            __syncthreads();

            if (ch + 2 < NCH) {
                int nb = buf + 2; if (nb >= NBUF) nb -= NBUF;
                stage(ch + 2, nb);
            }

            // compute over As[buf]
            #pragma unroll
            for (int kt4 = 0; kt4 < 4; kt4++) {
                const int kb = kt4 * 8 + lk;
                uint32_t a[4];
                a[0] = tf32u(As[sw_idx(buf, rb,     kb    )]);
                a[1] = tf32u(As[sw_idx(buf, rb + 8, kb    )]);
                a[2] = tf32u(As[sw_idx(buf, rb,     kb + 4)]);
                a[3] = tf32u(As[sw_idx(buf, rb + 8, kb + 4)]);

                const int ktg = ch * 4 + kt4;
                #pragma unroll
                for (int g = 0; g < 4; g++) {
                    float2 bv = wbase[((size_t)g * 160u + ktg) * 32u];
                    mma_tf32(acc[g], a, bv);
                }
            }

            buf++; if (buf >= NBUF) buf = 0;
        }

        // gates + cell update + h write (in-register gate fusion)
        float* hout = g_h[(t + 1) & 1];
        float hv[4];
        #pragma unroll
        for (int q = 0; q < 4; q++) {
            float zg = acc[0][q] + bias[0][q & 1];
            float zi = acc[1][q] + bias[1][q & 1];
            float zf = acc[2][q] + bias[2][q & 1];
            float zo = acc[3][q] + bias[3][q & 1];
            float gg = tanh_f(zg);
            float ii = sig_f(zi);
            float ff = sig_f(zf);
            float oo = sig_f(zo);
            float c  = gg * ii + creg[q] * ff;
            creg[q] = c;
            hv[q] = tanh_f(c) * oo;
        }
        // rows rb (q0,q1) and rb+8 (q2,q3), cols j0, j0+1 (contiguous)
        *(float2*)&hout[rb * HID + j0]       = make_float2(hv[0], hv[1]);
        *(float2*)&hout[(rb + 8) * HID + j0] = make_float2(hv[2], hv[3]);

        grid_bar((unsigned)(t + 2) * NCTA);
    }

    // final projection: out = h_T @ W_ph + b_p  (h_T lives in g_h[0], T=512 even)
    const float* hfin = g_h[0];
    const int gw = cta * 8 + wid;              // 0..1023 global warp id
    for (int e = gw; e < BATCH * COUT; e += NCTA * 8) {
        const int b  = e / COUT;
        const int cc = e - b * COUT;
        float s = 0.0f;
        for (int j = lane; j < HID; j += 32)
            s += hfin[b * HID + j] * Wph[j * COUT + cc];
        #pragma unroll
        for (int off = 16; off; off >>= 1)
            s += __shfl_down_sync(0xFFFFFFFFu, s, off);
        if (lane == 0) out[e] = s + bp[cc];
    }
}

// ---------------- launch ----------------
extern "C" void kernel_launch(void* const* d_in, const int* in_sizes, int n_in,
                              void* d_out, int out_size)
{
    const float* x = (const float*)d_in[0];
    const float *Wgx, *Wix, *Wfx, *Wox, *Wgh, *Wih, *Wfh, *Woh;
    const float *bg, *bi, *bf_, *bo, *Wph, *bp;

    // Detect input ordering from sizes (setup_inputs dict order vs signature order).
    if (in_sizes[2] == HID * HID) {
        Wgx = (const float*)d_in[1];  Wgh = (const float*)d_in[2];  bg  = (const float*)d_in[3];
        Wix = (const float*)d_in[4];  Wih = (const float*)d_in[5];  bi  = (const float*)d_in[6];
        Wfx = (const float*)d_in[7];  Wfh = (const float*)d_in[8];  bf_ = (const float*)d_in[9];
        Wox = (const float*)d_in[10]; Woh = (const float*)d_in[11]; bo  = (const float*)d_in[12];
        Wph = (const float*)d_in[13]; bp  = (const float*)d_in[14];
    } else {
        Wgx = (const float*)d_in[1];  Wix = (const float*)d_in[2];
        Wfx = (const float*)d_in[3];  Wox = (const float*)d_in[4];
        Wgh = (const float*)d_in[5];  Wih = (const float*)d_in[6];
        Wfh = (const float*)d_in[7];  Woh = (const float*)d_in[8];
        bg  = (const float*)d_in[9];  bi  = (const float*)d_in[10];
        bf_ = (const float*)d_in[11]; bo  = (const float*)d_in[12];
        Wph = (const float*)d_in[13]; bp  = (const float*)d_in[14];
    }

    // pack weights into fragment layout + reset barrier (runs every replay)
    const unsigned total = 512u * 160u * 32u;
    pack_kernel<<<(total + 255) / 256, 256>>>(Wgx, Wix, Wfx, Wox,
                                              Wgh, Wih, Wfh, Woh,
                                              bg, bi, bf_, bo);

    lstm_kernel<<<NCTA, NTHR>>>(x, Wph, bp, (float*)d_out);
}

// round 5
// speedup vs baseline: 2.0209x; 1.3586x over previous
#include <cuda_runtime.h>
#include <cstdint>
#include <cstddef>

#define SEQ   512
#define DIM   256
#define HID   1024
#define BATCH 128
#define KTOT  1280
#define TSTEP 512
#define COUT  10

#define NCTA  128
#define NTHR  512
#define CH_K  32            // K-chunk per stage
#define NCHG  20            // chunks per warp-group (K/2 / 32)
#define KHALF 640

// smem layout (dynamic): [0, 160KB) weight frags, [160KB, 224KB) A buffers (4x16KB)
#define WS_F2   (4 * 160 * 32)             // 20480 float2 = 160 KB
#define AS_OFF  (WS_F2 * 8)                // byte offset of A region
#define SMEM_BYTES (AS_OFF + 4 * BATCH * 32 * 4)   // 229376 B

// ---------------- device scratch (no allocations allowed) ----------------
__device__ float2   g_Wf[512u * 160u * 32u];   // packed B fragments (21 MB)
__device__ float    g_bcat[4 * HID];           // fused bias
__device__ float    g_h[2][BATCH * HID];       // double-buffered hidden state
__device__ unsigned g_bar;                     // monotonic grid barrier counter

// ---------------- helpers ----------------
__device__ __forceinline__ uint32_t tf32u(float x) {
    uint32_t u;
    asm("cvt.rna.tf32.f32 %0, %1;" : "=r"(u) : "f"(x));
    return u;
}
__device__ __forceinline__ float tf32_rn(float x) { return __uint_as_float(tf32u(x)); }

__device__ __forceinline__ float sig_f(float x) {
    float ax = fabsf(x);
    float e  = __expf(-ax);
    float s  = __fdividef(1.0f, 1.0f + e);
    return (x >= 0.0f) ? s : (1.0f - s);
}

__device__ __forceinline__ float tanh_f(float x) {
    float ax = fabsf(x);
    float e  = __expf(-2.0f * ax);
    float t  = __fdividef(1.0f - e, 1.0f + e);
    return copysignf(t, x);
}

__device__ __forceinline__ void grid_bar(unsigned target) {
    __syncthreads();
    if (threadIdx.x == 0) {
        __threadfence();                       // release this CTA's writes
        atomicAdd(&g_bar, 1u);
        unsigned v;
        do {
            asm volatile("ld.global.acquire.gpu.u32 %0, [%1];"
                         : "=r"(v) : "l"(&g_bar));
        } while (v < target);
    }
    __syncthreads();
}

__device__ __forceinline__ void mma_tf32(float* c, const uint32_t* a, float2 b) {
    uint32_t b0 = __float_as_uint(b.x);
    uint32_t b1 = __float_as_uint(b.y);
    asm volatile(
        "mma.sync.aligned.m16n8k8.row.col.f32.tf32.tf32.f32 "
        "{%0,%1,%2,%3}, {%4,%5,%6,%7}, {%8,%9}, {%0,%1,%2,%3};\n"
        : "+f"(c[0]), "+f"(c[1]), "+f"(c[2]), "+f"(c[3])
        : "r"(a[0]), "r"(a[1]), "r"(a[2]), "r"(a[3]), "r"(b0), "r"(b1));
}

// swizzled A index: 128B rows, 16B-block XOR swizzle -> conflict-free frag reads
__device__ __forceinline__ int sw_idx(int bufIdx, int row, int kb) {
    return (bufIdx * BATCH + row) * 32 + ((((kb >> 2) ^ (row & 7)) << 2) | (kb & 3));
}

// ---------------- setup: pack W into mma-B fragment layout (tf32, RN) ----------------
__global__ void pack_kernel(
    const float* __restrict__ Wgx, const float* __restrict__ Wix,
    const float* __restrict__ Wfx, const float* __restrict__ Wox,
    const float* __restrict__ Wgh, const float* __restrict__ Wih,
    const float* __restrict__ Wfh, const float* __restrict__ Woh,
    const float* __restrict__ bg,  const float* __restrict__ bi,
    const float* __restrict__ bf_, const float* __restrict__ bo)
{
    unsigned idx = blockIdx.x * blockDim.x + threadIdx.x;
    if (idx == 0) g_bar = 0u;                  // reset barrier each replay
    if (idx < 4u * HID) {
        int gate = idx >> 10, j = idx & (HID - 1);
        const float* bp = (gate == 0) ? bg : (gate == 1) ? bi : (gate == 2) ? bf_ : bo;
        g_bcat[idx] = bp[j];
    }
    if (idx >= 512u * 160u * 32u) return;

    int lane = idx & 31;
    unsigned rest = idx >> 5;
    int kt  = rest % 160;                      // 8-k group 0..159
    int gt  = rest / 160;                      // cta*4 + gate
    int cta  = gt >> 2;
    int gate = gt & 3;
    int j = cta * 8 + (lane >> 2);
    int k = kt * 8 + (lane & 3);               // r0: k, r1: k+4

    const float* Wx = (gate == 0) ? Wgx : (gate == 1) ? Wix : (gate == 2) ? Wfx : Wox;
    const float* Wh = (gate == 0) ? Wgh : (gate == 1) ? Wih : (gate == 2) ? Wfh : Woh;

    float v0, v1;
    if (k < DIM) { v0 = Wx[k * HID + j];          v1 = Wx[(k + 4) * HID + j]; }
    else         { v0 = Wh[(k - DIM) * HID + j];  v1 = Wh[(k + 4 - DIM) * HID + j]; }

    g_Wf[idx] = make_float2(tf32_rn(v0), tf32_rn(v1));
}

// ---------------- persistent LSTM kernel ----------------
__global__ void __launch_bounds__(NTHR, 1)
lstm_kernel(const float* __restrict__ x,
            const float* __restrict__ Wph,
            const float* __restrict__ bp,
            float* __restrict__ out)
{
    extern __shared__ __align__(16) char smem_[];
    float2* ws = (float2*)smem_;                       // weight fragments (smem-resident)
    float*  As = (float*)(smem_ + AS_OFF);             // A tiles, 4 buffers (2 per group)
    float*  red = As;                                  // reduction area (reused post-loop)

    const int tid   = threadIdx.x;
    const int cta   = blockIdx.x;
    const int wid   = tid >> 5;
    const int lane  = tid & 31;
    const int gid   = wid >> 3;                // K-half group 0/1
    const int wrow  = wid & 7;
    const int lk    = lane & 3;
    const int lg    = lane >> 2;

    // staging: 256 threads per group stage that group's 128x32 chunk
    const int ltid = tid & 255;
    const int srow = ltid >> 1;                // 0..127
    const int sk4  = (ltid & 1) * 16;          // 0 or 16
    const uint32_t as_sbase =
        (uint32_t)__cvta_generic_to_shared(As) + (uint32_t)(srow * 32) * 4u;

    // copy this CTA's weight slice into smem (once; persists across all steps)
    {
        const float2* src = g_Wf + (size_t)(cta * 4) * 160u * 32u;
        for (int i = tid; i < WS_F2; i += NTHR) ws[i] = src[i];
    }

    // zero h0
    for (int i = cta * NTHR + tid; i < BATCH * HID; i += NCTA * NTHR)
        g_h[0][i] = 0.0f;
    grid_bar(1u * NCTA);

    // per-thread persistent cell state + bias (group 0 owns the cell state)
    float creg[4];
    #pragma unroll
    for (int q = 0; q < 4; q++) creg[q] = 0.0f;

    const int j0 = cta * 8 + 2 * lk;
    float bias[4][2];
    #pragma unroll
    for (int g = 0; g < 4; g++) {
        bias[g][0] = g_bcat[g * HID + j0];
        bias[g][1] = g_bcat[g * HID + j0 + 1];
    }

    const int rb = wrow * 16 + lg;             // warp covers rows wrow*16..+15

    for (int t = 0; t < TSTEP; t++) {
        float acc[4][4];
        #pragma unroll
        for (int g = 0; g < 4; g++)
            #pragma unroll
            for (int q = 0; q < 4; q++) acc[g][q] = 0.0f;

        const float* hin = g_h[t & 1];

        // stage chunk ch (group-local) into buffer bf of this group
        auto stage = [&](int ch, int bf) {
            const int kg = gid * KHALF + ch * CH_K + sk4;
            const float* s = (kg < DIM)
                ? x + ((size_t)srow * SEQ + (size_t)t) * DIM + kg
                : hin + srow * HID + (kg - DIM);
            const uint32_t dbase =
                as_sbase + (uint32_t)((gid * 2 + bf) * BATCH * 32) * 4u;
            #pragma unroll
            for (int i = 0; i < 4; i++) {
                int b  = (sk4 >> 2) + i;               // 16B block 0..7
                int sb = b ^ (srow & 7);
                asm volatile("cp.async.cg.shared.global [%0], [%1], 16;\n"
                             :: "r"(dbase + (uint32_t)sb * 16u), "l"(s + 4 * i)
                             : "memory");
            }
            asm volatile("cp.async.commit_group;\n" ::: "memory");
        };

        stage(0, 0);                           // prologue

        for (int ch = 0; ch < NCHG; ch++) {
            asm volatile("cp.async.wait_group 0;\n" ::: "memory");
            __syncthreads();                   // chunk ch visible; prev compute done

            if (ch + 1 < NCHG) stage(ch + 1, (ch + 1) & 1);  // overlaps compute

            const int bufIdx = gid * 2 + (ch & 1);
            #pragma unroll
            for (int kt4 = 0; kt4 < 4; kt4++) {
                const int kb = kt4 * 8 + lk;
                uint32_t a[4];
                a[0] = tf32u(As[sw_idx(bufIdx, rb,     kb    )]);
                a[1] = tf32u(As[sw_idx(bufIdx, rb + 8, kb    )]);
                a[2] = tf32u(As[sw_idx(bufIdx, rb,     kb + 4)]);
                a[3] = tf32u(As[sw_idx(bufIdx, rb + 8, kb + 4)]);

                const int ktg = gid * 80 + ch * 4 + kt4;
                #pragma unroll
                for (int g = 0; g < 4; g++) {
                    float2 bv = ws[((size_t)(g * 160 + ktg)) * 32u + lane];
                    mma_tf32(acc[g], a, bv);
                }
            }
        }

        // cross-group K reduction through smem, then gates (group 0 finishes)
        __syncthreads();                       // all compute done; A bufs reusable
        if (gid == 1) {
            float* r = red + (size_t)(tid - 256) * 16;
            #pragma unroll
            for (int g = 0; g < 4; g++)
                #pragma unroll
                for (int q = 0; q < 4; q++) r[g * 4 + q] = acc[g][q];
        }
        __syncthreads();

        if (gid == 0) {
            const float* r = red + (size_t)tid * 16;
            float* hout = g_h[(t + 1) & 1];
            float hv[4];
            #pragma unroll
            for (int q = 0; q < 4; q++) {
                float zg = acc[0][q] + r[0 * 4 + q] + bias[0][q & 1];
                float zi = acc[1][q] + r[1 * 4 + q] + bias[1][q & 1];
                float zf = acc[2][q] + r[2 * 4 + q] + bias[2][q & 1];
                float zo = acc[3][q] + r[3 * 4 + q] + bias[3][q & 1];
                float gg = tanh_f(zg);
                float ii = sig_f(zi);
                float ff = sig_f(zf);
                float oo = sig_f(zo);
                float c  = gg * ii + creg[q] * ff;
                creg[q] = c;
                hv[q] = tanh_f(c) * oo;
            }
            *(float2*)&hout[rb * HID + j0]       = make_float2(hv[0], hv[1]);
            *(float2*)&hout[(rb + 8) * HID + j0] = make_float2(hv[2], hv[3]);
        }

        grid_bar((unsigned)(t + 2) * NCTA);
    }

    // final projection: out = h_T @ W_ph + b_p  (h_T lives in g_h[0], T even)
    const float* hfin = g_h[0];
    const int gw = cta * 16 + wid;             // 0..2047 global warp id
    for (int e = gw; e < BATCH * COUT; e += NCTA * 16) {
        const int b  = e / COUT;
        const int cc = e - b * COUT;
        float s = 0.0f;
        for (int j = lane; j < HID; j += 32)
            s += hfin[b * HID + j] * Wph[j * COUT + cc];
        #pragma unroll
        for (int off = 16; off; off >>= 1)
            s += __shfl_down_sync(0xFFFFFFFFu, s, off);
        if (lane == 0) out[e] = s + bp[cc];
    }
}

// ---------------- launch ----------------
extern "C" void kernel_launch(void* const* d_in, const int* in_sizes, int n_in,
                              void* d_out, int out_size)
{
    const float* x = (const float*)d_in[0];
    const float *Wgx, *Wix, *Wfx, *Wox, *Wgh, *Wih, *Wfh, *Woh;
    const float *bg, *bi, *bf_, *bo, *Wph, *bp;

    // Detect input ordering from sizes (setup_inputs dict order vs signature order).
    if (in_sizes[2] == HID * HID) {
        Wgx = (const float*)d_in[1];  Wgh = (const float*)d_in[2];  bg  = (const float*)d_in[3];
        Wix = (const float*)d_in[4];  Wih = (const float*)d_in[5];  bi  = (const float*)d_in[6];
        Wfx = (const float*)d_in[7];  Wfh = (const float*)d_in[8];  bf_ = (const float*)d_in[9];
        Wox = (const float*)d_in[10]; Woh = (const float*)d_in[11]; bo  = (const float*)d_in[12];
        Wph = (const float*)d_in[13]; bp  = (const float*)d_in[14];
    } else {
        Wgx = (const float*)d_in[1];  Wix = (const float*)d_in[2];
        Wfx = (const float*)d_in[3];  Wox = (const float*)d_in[4];
        Wgh = (const float*)d_in[5];  Wih = (const float*)d_in[6];
        Wfh = (const float*)d_in[7];  Woh = (const float*)d_in[8];
        bg  = (const float*)d_in[9];  bi  = (const float*)d_in[10];
        bf_ = (const float*)d_in[11]; bo  = (const float*)d_in[12];
        Wph = (const float*)d_in[13]; bp  = (const float*)d_in[14];
    }

    const unsigned total = 512u * 160u * 32u;
    pack_kernel<<<(total + 255) / 256, 256>>>(Wgx, Wix, Wfx, Wox,
                                              Wgh, Wih, Wfh, Woh,
                                              bg, bi, bf_, bo);

    static bool attr_set = false;
    if (!attr_set) {
        cudaFuncSetAttribute(lstm_kernel,
                             cudaFuncAttributeMaxDynamicSharedMemorySize,
                             SMEM_BYTES);
        attr_set = true;
    }
    lstm_kernel<<<NCTA, NTHR, SMEM_BYTES>>>(x, Wph, bp, (float*)d_out);
}

// round 7
// speedup vs baseline: 2.4314x; 1.2032x over previous
#include <cuda_runtime.h>
#include <cstdint>
#include <cstddef>

#define SEQ   512
#define DIM   256
#define HID   1024
#define BATCH 128
#define KTOT  1280
#define TSTEP 512
#define COUT  10

#define NCTA  128
#define NTHR  1024
#define CH_K  32            // K-chunk per stage
#define NCHG  20            // chunks per k-group (640 / 32)
#define KHALF 640

// smem layout (bytes): [32,160) bias, [1024, 164864) weights, then 4 A buffers
#define SM_BIAS  32
#define SM_W     1024
#define W_BYTES  (4 * 160 * 32 * 8)            // 163840 (4 gates x 160 ktg x 32 lanes x float2)
#define SM_A     (SM_W + W_BYTES)              // 164864
#define A_BYTES  (BATCH * CH_K * 4)            // 16384
#define SMEM_BYTES (SM_A + 4 * A_BYTES)        // 230400

// ---------------- device scratch (no allocations allowed) ----------------
__device__ float2   g_Wf[512u * 160u * 32u];   // packed B fragments (21 MB)
__device__ float    g_bcat[4 * HID];           // fused bias
__device__ float    g_h[2][BATCH * HID];       // double-buffered hidden state
__device__ unsigned g_bar;                     // monotonic grid barrier counter

// ---------------- helpers ----------------
__device__ __forceinline__ uint32_t tf32u(float x) {
    uint32_t u;
    asm("cvt.rna.tf32.f32 %0, %1;" : "=r"(u) : "f"(x));
    return u;
}
__device__ __forceinline__ float tf32_rn(float x) { return __uint_as_float(tf32u(x)); }

__device__ __forceinline__ float sig_f(float x) {
    float ax = fabsf(x);
    float e  = __expf(-ax);
    float s  = __fdividef(1.0f, 1.0f + e);
    return (x >= 0.0f) ? s : (1.0f - s);
}
__device__ __forceinline__ float tanh_f(float x) {
    float ax = fabsf(x);
    float e  = __expf(-2.0f * ax);
    float t  = __fdividef(1.0f - e, 1.0f + e);
    return copysignf(t, x);
}
__device__ __forceinline__ void grid_bar(unsigned target) {
    __syncthreads();
    if (threadIdx.x == 0) {
        __threadfence();
        atomicAdd(&g_bar, 1u);
        unsigned v;
        do {
            asm volatile("ld.global.acquire.gpu.u32 %0, [%1];" : "=r"(v) : "l"(&g_bar));
        } while (v < target);
    }
    __syncthreads();
}
__device__ __forceinline__ void mma_tf32(float* c, const uint32_t* a, float2 b) {
    uint32_t b0 = __float_as_uint(b.x);
    uint32_t b1 = __float_as_uint(b.y);
    asm volatile(
        "mma.sync.aligned.m16n8k8.row.col.f32.tf32.tf32.f32 "
        "{%0,%1,%2,%3}, {%4,%5,%6,%7}, {%8,%9}, {%0,%1,%2,%3};\n"
        : "+f"(c[0]), "+f"(c[1]), "+f"(c[2]), "+f"(c[3])
        : "r"(a[0]), "r"(a[1]), "r"(a[2]), "r"(a[3]), "r"(b0), "r"(b1));
}

// ---------------- setup: pack W into mma-B fragment layout (tf32, RN) ----------------
__global__ void pack_kernel(
    const float* __restrict__ Wgx, const float* __restrict__ Wix,
    const float* __restrict__ Wfx, const float* __restrict__ Wox,
    const float* __restrict__ Wgh, const float* __restrict__ Wih,
    const float* __restrict__ Wfh, const float* __restrict__ Woh,
    const float* __restrict__ bg,  const float* __restrict__ bi,
    const float* __restrict__ bf_, const float* __restrict__ bo)
{
    unsigned idx = blockIdx.x * blockDim.x + threadIdx.x;
    if (idx == 0) g_bar = 0u;                  // reset barrier each replay
    if (idx < 4u * HID) {
        int gate = idx >> 10, j = idx & (HID - 1);
        const float* bp = (gate == 0) ? bg : (gate == 1) ? bi : (gate == 2) ? bf_ : bo;
        g_bcat[idx] = bp[j];
    }
    if (idx >= 512u * 160u * 32u) return;

    int lane = idx & 31;
    unsigned rest = idx >> 5;
    int kt  = rest % 160;                      // 8-k group 0..159
    int gt  = rest / 160;                      // cta*4 + gate
    int cta  = gt >> 2;
    int gate = gt & 3;
    int j = cta * 8 + (lane >> 2);
    int k = kt * 8 + (lane & 3);               // r0: k, r1: k+4

    const float* Wx = (gate == 0) ? Wgx : (gate == 1) ? Wix : (gate == 2) ? Wfx : Wox;
    const float* Wh = (gate == 0) ? Wgh : (gate == 1) ? Wih : (gate == 2) ? Wfh : Woh;

    float v0, v1;
    if (k < DIM) { v0 = Wx[k * HID + j];          v1 = Wx[(k + 4) * HID + j]; }
    else         { v0 = Wh[(k - DIM) * HID + j];  v1 = Wh[(k + 4 - DIM) * HID + j]; }

    g_Wf[idx] = make_float2(tf32_rn(v0), tf32_rn(v1));
}

// ---------------- persistent LSTM kernel ----------------
__global__ void __launch_bounds__(NTHR, 1)
lstm_kernel(const float* __restrict__ x,
            const float* __restrict__ Wph,
            const float* __restrict__ bp,
            float* __restrict__ out)
{
    extern __shared__ __align__(1024) char smem[];
    const uint32_t sbase = (uint32_t)__cvta_generic_to_shared(smem);
    float*  bias_sm = (float*)(smem + SM_BIAS);
    float2* ws = (float2*)(smem + SM_W);
    float*  As = (float*)(smem + SM_A);
    float*  red = As;                          // partial-sum area (reused post-loop)

    const int tid   = threadIdx.x;
    const int cta   = blockIdx.x;
    const int wid   = tid >> 5;
    const int lane  = tid & 31;
    const int gid   = tid >> 9;                // K-half group 0/1
    const int ng    = (wid >> 3) & 1;          // gate-pair group 0/1
    const int wrow  = wid & 7;                 // m-row group 0..7
    const int lk    = lane & 3;
    const int lg    = lane >> 2;

    // staging: 512 threads per k-group stage that group's 128x32 chunk (32B each)
    const int ltid = tid & 511;
    const int srow = ltid >> 2;                // 0..127
    const int q4   = ltid & 3;                 // 8-float slice within 32-k row

    // weight copy (once; persists), bias, zero h0
    {
        const float4* src = (const float4*)(g_Wf + (size_t)(cta * 4) * 160u * 32u);
        float4* dst = (float4*)ws;
        for (int i = tid; i < W_BYTES / 16; i += NTHR) dst[i] = src[i];
    }
    if (tid < 32)
        bias_sm[tid] = g_bcat[(tid >> 3) * HID + cta * 8 + (tid & 7)];
    for (int i = cta * NTHR + tid; i < BATCH * HID; i += NCTA * NTHR)
        g_h[0][i] = 0.0f;
    __syncthreads();
    grid_bar(1u * NCTA);

    float creg[4];
    #pragma unroll
    for (int q = 0; q < 4; q++) creg[q] = 0.0f;

    const int j0 = cta * 8 + 2 * lk;
    const int rb = wrow * 16 + lg;

    for (int t = 0; t < TSTEP; t++) {
        float acc[2][4];
        #pragma unroll
        for (int g = 0; g < 2; g++)
            #pragma unroll
            for (int q = 0; q < 4; q++) acc[g][q] = 0.0f;

        const float* hin = g_h[t & 1];

        // stage chunk c (k-group local) into buffer bf of this group
        auto stage = [&](int c, int bf) {
            const int kg = gid * KHALF + c * CH_K + q4 * 8;
            const float* s = (kg < DIM)
                ? x + ((size_t)srow * SEQ + (size_t)t) * DIM + kg
                : hin + (size_t)srow * HID + (kg - DIM);
            const uint32_t dbase = sbase + SM_A
                + (uint32_t)((gid * 2 + bf) * A_BYTES) + (uint32_t)srow * 128u;
            #pragma unroll
            for (int i = 0; i < 2; i++) {
                int b = q4 * 2 + i;            // 16B block 0..7
                asm volatile("cp.async.cg.shared.global [%0], [%1], 16;"
                             :: "r"(dbase + (uint32_t)((b ^ (srow & 7)) * 16)),
                                "l"(s + 4 * i) : "memory");
            }
            asm volatile("cp.async.commit_group;" ::: "memory");
        };

        stage(0, 0);                           // prologue

        for (int c = 0; c < NCHG; c++) {
            asm volatile("cp.async.wait_group 0;" ::: "memory");
            __syncthreads();                   // chunk c staged; prev compute done

            if (c + 1 < NCHG) stage(c + 1, (c + 1) & 1);   // overlaps compute

            const int bufW = (gid * 2 + (c & 1)) * BATCH * 32;
            #pragma unroll
            for (int kt4 = 0; kt4 < 4; kt4++) {
                const int kb = kt4 * 8 + lk;
                const int s0 = ((kb >> 2) ^ (rb & 7)) << 2 | (kb & 3);
                const int s1 = (((kb + 4) >> 2) ^ (rb & 7)) << 2 | (kb & 3);
                const int s2 = ((kb >> 2) ^ ((rb + 8) & 7)) << 2 | (kb & 3);
                const int s3 = (((kb + 4) >> 2) ^ ((rb + 8) & 7)) << 2 | (kb & 3);
                uint32_t a[4];
                a[0] = tf32u(As[bufW + rb * 32 + s0]);
                a[1] = tf32u(As[bufW + (rb + 8) * 32 + s2]);
                a[2] = tf32u(As[bufW + rb * 32 + s1]);
                a[3] = tf32u(As[bufW + (rb + 8) * 32 + s3]);

                const int ktg = gid * 80 + c * 4 + kt4;
                #pragma unroll
                for (int g = 0; g < 2; g++) {
                    float2 bv = ws[((size_t)((2 * ng + g) * 160 + ktg)) * 32u + lane];
                    mma_tf32(acc[g], a, bv);
                }
            }
        }

        // cross-group reduction through smem, gates by threads 0-255 (k0,n0)
        __syncthreads();                       // all compute done; A bufs reusable
        if (tid >= 256) {
            float* r = red + (size_t)((tid >> 8) - 1) * 2048 + (size_t)(tid & 255) * 8;
            #pragma unroll
            for (int q = 0; q < 4; q++) { r[q] = acc[0][q]; r[4 + q] = acc[1][q]; }
        }
        __syncthreads();

        if (tid < 256) {
            const float* r1 = red +           (size_t)tid * 8;   // (k0,n1): gates f,o
            const float* r2 = red + 2048 +    (size_t)tid * 8;   // (k1,n0): gates g,i
            const float* r3 = red + 4096 +    (size_t)tid * 8;   // (k1,n1): gates f,o
            float* hout = g_h[(t + 1) & 1];
            float hv[4];
            #pragma unroll
            for (int q = 0; q < 4; q++) {
                const int bq = 2 * lk + (q & 1);
                float zg = acc[0][q] + r2[q]     + bias_sm[bq];
                float zi = acc[1][q] + r2[4 + q] + bias_sm[8 + bq];
                float zf = r1[q]     + r3[q]     + bias_sm[16 + bq];
                float zo = r1[4 + q] + r3[4 + q] + bias_sm[24 + bq];
                float c2 = tanh_f(zg) * sig_f(zi) + creg[q] * sig_f(zf);
                creg[q] = c2;
                hv[q] = tanh_f(c2) * sig_f(zo);
            }
            *(float2*)&hout[rb * HID + j0]       = make_float2(hv[0], hv[1]);
            *(float2*)&hout[(rb + 8) * HID + j0] = make_float2(hv[2], hv[3]);
        }

        grid_bar((unsigned)(t + 2) * NCTA);
    }

    // final projection: out = h_T @ W_ph + b_p (h_T in g_h[0], T even)
    const float* hfin = g_h[0];
    const int gw = cta * 32 + wid;
    for (int e = gw; e < BATCH * COUT; e += NCTA * 32) {
        const int b  = e / COUT;
        const int cc = e - b * COUT;
        float s = 0.0f;
        for (int j = lane; j < HID; j += 32)
            s += hfin[b * HID + j] * Wph[j * COUT + cc];
        #pragma unroll
        for (int off = 16; off; off >>= 1)
            s += __shfl_down_sync(0xFFFFFFFFu, s, off);
        if (lane == 0) out[e] = s + bp[cc];
    }
}

// ---------------- launch ----------------
extern "C" void kernel_launch(void* const* d_in, const int* in_sizes, int n_in,
                              void* d_out, int out_size)
{
    const float* x = (const float*)d_in[0];
    const float *Wgx, *Wix, *Wfx, *Wox, *Wgh, *Wih, *Wfh, *Woh;
    const float *bg, *bi, *bf_, *bo, *Wph, *bp;

    if (in_sizes[2] == HID * HID) {   // setup_inputs dict order
        Wgx = (const float*)d_in[1];  Wgh = (const float*)d_in[2];  bg  = (const float*)d_in[3];
        Wix = (const float*)d_in[4];  Wih = (const float*)d_in[5];  bi  = (const float*)d_in[6];
        Wfx = (const float*)d_in[7];  Wfh = (const float*)d_in[8];  bf_ = (const float*)d_in[9];
        Wox = (const float*)d_in[10]; Woh = (const float*)d_in[11]; bo  = (const float*)d_in[12];
        Wph = (const float*)d_in[13]; bp  = (const float*)d_in[14];
    } else {                          // signature order
        Wgx = (const float*)d_in[1];  Wix = (const float*)d_in[2];
        Wfx = (const float*)d_in[3];  Wox = (const float*)d_in[4];
        Wgh = (const float*)d_in[5];  Wih = (const float*)d_in[6];
        Wfh = (const float*)d_in[7];  Woh = (const float*)d_in[8];
        bg  = (const float*)d_in[9];  bi  = (const float*)d_in[10];
        bf_ = (const float*)d_in[11]; bo  = (const float*)d_in[12];
        Wph = (const float*)d_in[13]; bp  = (const float*)d_in[14];
    }

    const unsigned total = 512u * 160u * 32u;
    pack_kernel<<<(total + 255) / 256, 256>>>(Wgx, Wix, Wfx, Wox,
                                              Wgh, Wih, Wfh, Woh,
                                              bg, bi, bf_, bo);

    static bool attr_set = false;
    if (!attr_set) {
        cudaFuncSetAttribute(lstm_kernel,
                             cudaFuncAttributeMaxDynamicSharedMemorySize,
                             SMEM_BYTES);
        attr_set = true;
    }
    lstm_kernel<<<NCTA, NTHR, SMEM_BYTES>>>(x, Wph, bp, (float*)d_out);
}

// round 8
// speedup vs baseline: 2.5596x; 1.0527x over previous
#include <cuda_runtime.h>
#include <cstdint>
#include <cstddef>

#define SEQ   512
#define DIM   256
#define HID   1024
#define BATCH 128
#define KTOT  1280
#define TSTEP 512
#define COUT  10

#define NCTA  128
#define NTHR  1024
#define CH_K  32            // K-chunk per stage
#define NCHG  20            // chunks per k-group (640 / 32)
#define KHALF 640

// smem layout (bytes): [32,160) bias, [1024, 164864) weights, then 4 A buffers
#define SM_BIAS  32
#define SM_W     1024
#define W_BYTES  (4 * 160 * 32 * 8)            // 163840
#define SM_A     (SM_W + W_BYTES)              // 164864
#define A_BYTES  (BATCH * CH_K * 4)            // 16384
#define SMEM_BYTES (SM_A + 4 * A_BYTES)        // 230400

// ---------------- device scratch (no allocations allowed) ----------------
__device__ float2   g_Wf[512u * 160u * 32u];   // packed B fragments (21 MB)
__device__ float    g_x2[(size_t)BATCH * SEQ * DIM];  // x pre-rounded to tf32 (64 MB)
__device__ float    g_bcat[4 * HID];           // fused bias
__device__ float    g_h[2][BATCH * HID];       // double-buffered hidden state
__device__ unsigned g_bar;                     // monotonic grid barrier counter

// ---------------- helpers ----------------
__device__ __forceinline__ float tf32_rn(float x) {
    uint32_t u;
    asm("cvt.rna.tf32.f32 %0, %1;" : "=r"(u) : "f"(x));
    return __uint_as_float(u);
}
__device__ __forceinline__ float sig_f(float x) {
    float ax = fabsf(x);
    float e  = __expf(-ax);
    float s  = __fdividef(1.0f, 1.0f + e);
    return (x >= 0.0f) ? s : (1.0f - s);
}
__device__ __forceinline__ float tanh_f(float x) {
    float ax = fabsf(x);
    float e  = __expf(-2.0f * ax);
    float t  = __fdividef(1.0f - e, 1.0f + e);
    return copysignf(t, x);
}
__device__ __forceinline__ void grid_bar(unsigned target) {
    __syncthreads();
    if (threadIdx.x == 0) {
        __threadfence();
        atomicAdd(&g_bar, 1u);
        unsigned v;
        do {
            asm volatile("ld.global.acquire.gpu.u32 %0, [%1];" : "=r"(v) : "l"(&g_bar));
        } while (v < target);
    }
    __syncthreads();
}
__device__ __forceinline__ void mma_tf32(float* c, const uint32_t* a, float2 b) {
    uint32_t b0 = __float_as_uint(b.x);
    uint32_t b1 = __float_as_uint(b.y);
    asm volatile(
        "mma.sync.aligned.m16n8k8.row.col.f32.tf32.tf32.f32 "
        "{%0,%1,%2,%3}, {%4,%5,%6,%7}, {%8,%9}, {%0,%1,%2,%3};\n"
        : "+f"(c[0]), "+f"(c[1]), "+f"(c[2]), "+f"(c[3])
        : "r"(a[0]), "r"(a[1]), "r"(a[2]), "r"(a[3]), "r"(b0), "r"(b1));
}

// ---------------- setup: pack W into mma-B fragment layout (tf32, RN) ----------------
__global__ void pack_kernel(
    const float* __restrict__ Wgx, const float* __restrict__ Wix,
    const float* __restrict__ Wfx, const float* __restrict__ Wox,
    const float* __restrict__ Wgh, const float* __restrict__ Wih,
    const float* __restrict__ Wfh, const float* __restrict__ Woh,
    const float* __restrict__ bg,  const float* __restrict__ bi,
    const float* __restrict__ bf_, const float* __restrict__ bo)
{
    unsigned idx = blockIdx.x * blockDim.x + threadIdx.x;
    if (idx == 0) g_bar = 0u;                  // reset barrier each replay
    if (idx < 4u * HID) {
        int gate = idx >> 10, j = idx & (HID - 1);
        const float* bp = (gate == 0) ? bg : (gate == 1) ? bi : (gate == 2) ? bf_ : bo;
        g_bcat[idx] = bp[j];
    }
    if (idx >= 512u * 160u * 32u) return;

    int lane = idx & 31;
    unsigned rest = idx >> 5;
    int kt  = rest % 160;                      // 8-k group 0..159
    int gt  = rest / 160;                      // cta*4 + gate
    int cta  = gt >> 2;
    int gate = gt & 3;
    int j = cta * 8 + (lane >> 2);
    int k = kt * 8 + (lane & 3);               // r0: k, r1: k+4

    const float* Wx = (gate == 0) ? Wgx : (gate == 1) ? Wix : (gate == 2) ? Wfx : Wox;
    const float* Wh = (gate == 0) ? Wgh : (gate == 1) ? Wih : (gate == 2) ? Wfh : Woh;

    float v0, v1;
    if (k < DIM) { v0 = Wx[k * HID + j];          v1 = Wx[(k + 4) * HID + j]; }
    else         { v0 = Wh[(k - DIM) * HID + j];  v1 = Wh[(k + 4 - DIM) * HID + j]; }

    g_Wf[idx] = make_float2(tf32_rn(v0), tf32_rn(v1));
}

__global__ void roundx_kernel(const float* __restrict__ x) {
    size_t n = (size_t)BATCH * SEQ * DIM;
    for (size_t i = (size_t)blockIdx.x * blockDim.x + threadIdx.x; i < n;
         i += (size_t)gridDim.x * blockDim.x)
        g_x2[i] = tf32_rn(x[i]);
}

// ---------------- persistent LSTM kernel ----------------
__global__ void __launch_bounds__(NTHR, 1)
lstm_kernel(const float* __restrict__ Wph,
            const float* __restrict__ bp,
            float* __restrict__ out)
{
    extern __shared__ __align__(1024) char smem[];
    const uint32_t sbase = (uint32_t)__cvta_generic_to_shared(smem);
    float*  bias_sm = (float*)(smem + SM_BIAS);
    float2* ws = (float2*)(smem + SM_W);
    const uint32_t* Au = (const uint32_t*)(smem + SM_A);
    float*  red = (float*)(smem + SM_A);       // partial-sum area (reused post-loop)

    const int tid   = threadIdx.x;
    const int cta   = blockIdx.x;
    const int wid   = tid >> 5;
    const int lane  = tid & 31;
    const int gid   = tid >> 9;                // K-half group 0/1
    const int ng    = (wid >> 3) & 1;          // gate-pair group 0/1
    const int wrow  = wid & 7;                 // m-row group 0..7
    const int lk    = lane & 3;
    const int lg    = lane >> 2;

    // staging: 512 threads per k-group stage that group's 128x32 chunk (32B each)
    const int ltid = tid & 511;
    const int srow = ltid >> 2;                // 0..127
    const int q4   = ltid & 3;                 // 8-float slice within 32-k row

    // weight copy (once; persists), bias, zero h0
    {
        const float4* src = (const float4*)(g_Wf + (size_t)(cta * 4) * 160u * 32u);
        float4* dst = (float4*)ws;
        for (int i = tid; i < W_BYTES / 16; i += NTHR) dst[i] = src[i];
    }
    if (tid < 32)
        bias_sm[tid] = g_bcat[(tid >> 3) * HID + cta * 8 + (tid & 7)];
    for (int i = cta * NTHR + tid; i < BATCH * HID; i += NCTA * NTHR)
        g_h[0][i] = 0.0f;
    __syncthreads();
    grid_bar(1u * NCTA);

    float creg[4];
    #pragma unroll
    for (int q = 0; q < 4; q++) creg[q] = 0.0f;

    const int j0 = cta * 8 + 2 * lk;
    const int rb = wrow * 16 + lg;

    // precomputed A-fragment offsets (word units). (rb+8)&7 == rb&7, so both
    // m-rows share in-row offsets; kb+4 offset is off ^ 4.
    const int e8 = rb & 7;
    int offk[4];
    #pragma unroll
    for (int kt4 = 0; kt4 < 4; kt4++)
        offk[kt4] = (((2 * kt4) ^ e8) << 2) | lk;
    const int rowA = rb * 32;
    const int rowB = rowA + 256;               // (rb+8)*32

    // weight fragment base for this warp's 2 gates and k-half
    const float2* wbase = ws + ((size_t)(2 * ng) * 160u + (size_t)gid * 80u) * 32u + lane;

    for (int t = 0; t < TSTEP; t++) {
        float acc[2][4];
        #pragma unroll
        for (int g = 0; g < 2; g++)
            #pragma unroll
            for (int q = 0; q < 4; q++) acc[g][q] = 0.0f;

        const float* hin = g_h[t & 1];

        // stage chunk c (k-group local) into buffer bf of this group
        auto stage = [&](int c, int bf) {
            const int kg = gid * KHALF + c * CH_K + q4 * 8;
            const float* s = (kg < DIM)
                ? g_x2 + ((size_t)srow * SEQ + (size_t)t) * DIM + kg
                : hin + (size_t)srow * HID + (kg - DIM);
            const uint32_t dbase = sbase + SM_A
                + (uint32_t)((gid * 2 + bf) * A_BYTES) + (uint32_t)srow * 128u;
            #pragma unroll
            for (int i = 0; i < 2; i++) {
                int b = q4 * 2 + i;            // 16B block 0..7
                asm volatile("cp.async.cg.shared.global [%0], [%1], 16;"
                             :: "r"(dbase + (uint32_t)((b ^ (srow & 7)) * 16)),
                                "l"(s + 4 * i) : "memory");
            }
            asm volatile("cp.async.commit_group;" ::: "memory");
        };

        stage(0, 0);                           // prologue

        for (int c = 0; c < NCHG; c++) {
            asm volatile("cp.async.wait_group 0;" ::: "memory");
            __syncthreads();                   // chunk c staged; prev compute done

            if (c + 1 < NCHG) stage(c + 1, (c + 1) & 1);   // overlaps compute

            const int bufW = (gid * 2 + (c & 1)) * (BATCH * 32);
            const uint32_t* Ab = Au + bufW;
            const float2*   wc = wbase + (size_t)(c * 4) * 32u;

            #pragma unroll
            for (int kt4 = 0; kt4 < 4; kt4++) {
                const int o0 = offk[kt4];
                uint32_t a[4];
                a[0] = Ab[rowA + o0];
                a[1] = Ab[rowB + o0];
                a[2] = Ab[rowA + (o0 ^ 4)];
                a[3] = Ab[rowB + (o0 ^ 4)];

                float2 bv0 = wc[(size_t)kt4 * 32u];
                float2 bv1 = wc[(size_t)(160 * 32) + (size_t)kt4 * 32u];
                mma_tf32(acc[0], a, bv0);
                mma_tf32(acc[1], a, bv1);
            }
        }

        // cross-group reduction through smem, gates by threads 0-255 (k0,n0)
        __syncthreads();                       // all compute done; A bufs reusable
        if (tid >= 256) {
            float* r = red + (size_t)((tid >> 8) - 1) * 2048 + (size_t)(tid & 255) * 8;
            #pragma unroll
            for (int q = 0; q < 4; q++) { r[q] = acc[0][q]; r[4 + q] = acc[1][q]; }
        }
        __syncthreads();

        if (tid < 256) {
            const float* r1 = red +        (size_t)tid * 8;   // (k0,n1): gates f,o
            const float* r2 = red + 2048 + (size_t)tid * 8;   // (k1,n0): gates g,i
            const float* r3 = red + 4096 + (size_t)tid * 8;   // (k1,n1): gates f,o
            float* hout = g_h[(t + 1) & 1];
            float hv[4];
            #pragma unroll
            for (int q = 0; q < 4; q++) {
                const int bq = 2 * lk + (q & 1);
                float zg = acc[0][q] + r2[q]     + bias_sm[bq];
                float zi = acc[1][q] + r2[4 + q] + bias_sm[8 + bq];
                float zf = r1[q]     + r3[q]     + bias_sm[16 + bq];
                float zo = r1[4 + q] + r3[4 + q] + bias_sm[24 + bq];
                float c2 = tanh_f(zg) * sig_f(zi) + creg[q] * sig_f(zf);
                creg[q] = c2;
                hv[q] = tf32_rn(tanh_f(c2) * sig_f(zo));   // RN: smem A is exact tf32
            }
            *(float2*)&hout[rb * HID + j0]       = make_float2(hv[0], hv[1]);
            *(float2*)&hout[(rb + 8) * HID + j0] = make_float2(hv[2], hv[3]);
        }

        grid_bar((unsigned)(t + 2) * NCTA);
    }

    // final projection: out = h_T @ W_ph + b_p (h_T in g_h[0], T even)
    const float* hfin = g_h[0];
    const int gw = cta * 32 + wid;
    for (int e = gw; e < BATCH * COUT; e += NCTA * 32) {
        const int b  = e / COUT;
        const int cc = e - b * COUT;
        float s = 0.0f;
        for (int j = lane; j < HID; j += 32)
            s += hfin[b * HID + j] * Wph[j * COUT + cc];
        #pragma unroll
        for (int off = 16; off; off >>= 1)
            s += __shfl_down_sync(0xFFFFFFFFu, s, off);
        if (lane == 0) out[e] = s + bp[cc];
    }
}

// ---------------- launch ----------------
extern "C" void kernel_launch(void* const* d_in, const int* in_sizes, int n_in,
                              void* d_out, int out_size)
{
    const float* x = (const float*)d_in[0];
    const float *Wgx, *Wix, *Wfx, *Wox, *Wgh, *Wih, *Wfh, *Woh;
    const float *bg, *bi, *bf_, *bo, *Wph, *bp;

    if (in_sizes[2] == HID * HID) {   // setup_inputs dict order
        Wgx = (const float*)d_in[1];  Wgh = (const float*)d_in[2];  bg  = (const float*)d_in[3];
        Wix = (const float*)d_in[4];  Wih = (const float*)d_in[5];  bi  = (const float*)d_in[6];
        Wfx = (const float*)d_in[7];  Wfh = (const float*)d_in[8];  bf_ = (const float*)d_in[9];
        Wox = (const float*)d_in[10]; Woh = (const float*)d_in[11]; bo  = (const float*)d_in[12];
        Wph = (const float*)d_in[13]; bp  = (const float*)d_in[14];
    } else {                          // signature order
        Wgx = (const float*)d_in[1];  Wix = (const float*)d_in[2];
        Wfx = (const float*)d_in[3];  Wox = (const float*)d_in[4];
        Wgh = (const float*)d_in[5];  Wih = (const float*)d_in[6];
        Wfh = (const float*)d_in[7];  Woh = (const float*)d_in[8];
        bg  = (const float*)d_in[9];  bi  = (const float*)d_in[10];
        bf_ = (const float*)d_in[11]; bo  = (const float*)d_in[12];
        Wph = (const float*)d_in[13]; bp  = (const float*)d_in[14];
    }

    const unsigned total = 512u * 160u * 32u;
    pack_kernel<<<(total + 255) / 256, 256>>>(Wgx, Wix, Wfx, Wox,
                                              Wgh, Wih, Wfh, Woh,
                                              bg, bi, bf_, bo);
    roundx_kernel<<<2048, 256>>>(x);

    static bool attr_set = false;
    if (!attr_set) {
        cudaFuncSetAttribute(lstm_kernel,
                             cudaFuncAttributeMaxDynamicSharedMemorySize,
                             SMEM_BYTES);
        attr_set = true;
    }
    lstm_kernel<<<NCTA, NTHR, SMEM_BYTES>>>(Wph, bp, (float*)d_out);
}